// round 12
// baseline (speedup 1.0000x reference)
#include <cuda_runtime.h>
#include <math.h>

#define MU   0.02f
#define MU2  (0.02f * 0.02f)
#define NBINS 10
#define MAXN  4194304
#define GRID_A 2048
#define GRID_B 1024
#define TPB   256
#define SUM_SCALE 1048576.0        // 2^20 fixed-point for deterministic u64 sums
#define FLT_MAX_C __uint_as_float(0x7F7FFFFFu)

// Static device scratch (no runtime allocation)
__device__ float2             gl_buf[MAXN];     // per row: (g, loss), fp32 exact
__device__ unsigned int       g_min_bits;       // g >= 0: uint order == float order
__device__ unsigned int       g_max_bits;
__device__ int                g_counts[NBINS];
__device__ unsigned long long g_sums[NBINS];    // loss sums, scaled by 2^20
__device__ unsigned int       g_done;           // pass-B completion counter

// ---------------------------------------------------------------------------
__global__ void init_kernel() {
    int t = threadIdx.x;
    if (t == 0) { g_min_bits = 0xFFFFFFFFu; g_max_bits = 0u; g_done = 0u; }
    if (t < NBINS) { g_counts[t] = 0; g_sums[t] = 0ull; }
}

// ---------------------------------------------------------------------------
// Per-channel: e = sqrt(d*d + mu*mu) with NO fma contraction (matches XLA).
__device__ __forceinline__ float denom_exact(float d) {
    return sqrtf(__fadd_rn(__fmul_rn(d, d), MU2));
}

// ---------------------------------------------------------------------------
// Pass A: per-row loss & g (exact fp32, XLA-matching op order), store
// interleaved, global min/max of g.
__global__ __launch_bounds__(TPB) void passA_kernel(
    const float4* __restrict__ inp, const float4* __restrict__ tgt, int N)
{
    const int stride = GRID_A * TPB;
    float lmin = FLT_MAX_C;
    float lmax = 0.0f;

    for (int i = blockIdx.x * TPB + threadIdx.x; i < N; i += stride) {
        float4 a = __ldcs(&inp[i]);
        float4 b = __ldcs(&tgt[i]);
        float d0 = a.x - b.x, d1 = a.y - b.y, d2 = a.z - b.z, d3 = a.w - b.w;
        float e0 = denom_exact(d0);
        float e1 = denom_exact(d1);
        float e2 = denom_exact(d2);
        float e3 = denom_exact(d3);
        // loss: sequential sum, matching jnp.sum over axis=1
        float loss = __fadd_rn(__fadd_rn(__fadd_rn(
                        (e0 - MU), (e1 - MU)), (e2 - MU)), (e3 - MU));
        // g: |d|/e per channel (IEEE division), sequential sum
        float t0 = __fdiv_rn(fabsf(d0), e0);
        float t1 = __fdiv_rn(fabsf(d1), e1);
        float t2 = __fdiv_rn(fabsf(d2), e2);
        float t3 = __fdiv_rn(fabsf(d3), e3);
        float g  = __fadd_rn(__fadd_rn(__fadd_rn(t0, t1), t2), t3);

        __stcg(&gl_buf[i], make_float2(g, loss));   // keep in L2 for pass B
        lmin = fminf(lmin, g);
        lmax = fmaxf(lmax, g);
    }

    // warp reduce min/max
    for (int off = 16; off > 0; off >>= 1) {
        lmin = fminf(lmin, __shfl_down_sync(0xFFFFFFFFu, lmin, off));
        lmax = fmaxf(lmax, __shfl_down_sync(0xFFFFFFFFu, lmax, off));
    }
    __shared__ float smin[TPB / 32], smax[TPB / 32];
    int wid = threadIdx.x >> 5, lid = threadIdx.x & 31;
    if (lid == 0) { smin[wid] = lmin; smax[wid] = lmax; }
    __syncthreads();
    if (wid == 0) {
        lmin = (lid < TPB / 32) ? smin[lid] : FLT_MAX_C;
        lmax = (lid < TPB / 32) ? smax[lid] : 0.0f;
        for (int off = 4; off > 0; off >>= 1) {
            lmin = fminf(lmin, __shfl_down_sync(0xFFFFFFFFu, lmin, off));
            lmax = fmaxf(lmax, __shfl_down_sync(0xFFFFFFFFu, lmax, off));
        }
        if (lid == 0) {
            atomicMin(&g_min_bits, __float_as_uint(lmin));
            atomicMax(&g_max_bits, __float_as_uint(lmax));
        }
    }
}

// ---------------------------------------------------------------------------
// Bin exactly as the reference: clip(floor((g / range) * 10), 0, 9)
__device__ __forceinline__ int bin_of(float g, float range) {
    float gn = __fmul_rn(__fdiv_rn(g, range), 10.0f);
    int b = __float2int_rd(gn);
    return max(0, min(NBINS - 1, b));
}

// ---------------------------------------------------------------------------
// Pass B: per-bin counts + loss sums, contention-free local accumulation,
// deterministic fixed-order block reduce, integer atomics. Last block finalizes.
__global__ __launch_bounds__(TPB) void passB_kernel(float* __restrict__ out, int N)
{
    const float range = __fsub_rn(__uint_as_float(g_max_bits),
                                  __uint_as_float(g_min_bits));

    float lsum[NBINS];
    int   lcnt[NBINS];
#pragma unroll
    for (int b = 0; b < NBINS; b++) { lsum[b] = 0.0f; lcnt[b] = 0; }

    const int gtid = blockIdx.x * TPB + threadIdx.x;
    const int gstride = GRID_B * TPB;
    const int N2 = N >> 1;
    const float4* gl4 = (const float4*)gl_buf;   // two rows per float4

    for (int i = gtid; i < N2; i += gstride) {
        float4 v = __ldcg(&gl4[i]);              // single-use stream: L2 fetch
        int b0 = bin_of(v.x, range);
        lsum[b0] += v.y; lcnt[b0] += 1;
        int b1 = bin_of(v.z, range);
        lsum[b1] += v.w; lcnt[b1] += 1;
    }
    for (int i = (N2 << 1) + gtid; i < N; i += gstride) {   // tail (odd N)
        float2 v = __ldcg(&gl_buf[i]);
        int b = bin_of(v.x, range);
        lsum[b] += v.y; lcnt[b] += 1;
    }

    // Deterministic fixed-order block reduction via shared memory
    __shared__ float ssum[NBINS][TPB];
    __shared__ int   scnt[NBINS][TPB];
    __shared__ float s2sum[NBINS][8];
    __shared__ int   s2cnt[NBINS][8];
#pragma unroll
    for (int b = 0; b < NBINS; b++) {
        ssum[b][threadIdx.x] = lsum[b];
        scnt[b][threadIdx.x] = lcnt[b];
    }
    __syncthreads();
    if (threadIdx.x < NBINS * 8) {
        int b = threadIdx.x >> 3, c = threadIdx.x & 7;
        float fs = 0.0f; int ic = 0;
        int base = c * 32;
        for (int j = 0; j < 32; j++) { fs += ssum[b][base + j]; ic += scnt[b][base + j]; }
        s2sum[b][c] = fs; s2cnt[b][c] = ic;
    }
    __syncthreads();
    if (threadIdx.x < NBINS) {
        int b = threadIdx.x;
        float fs = 0.0f; int ic = 0;
        for (int c = 0; c < 8; c++) { fs += s2sum[b][c]; ic += s2cnt[b][c]; }
        if (ic > 0) {
            atomicAdd(&g_counts[b], ic);
            long long q = llrint((double)fs * SUM_SCALE);
            atomicAdd(&g_sums[b], (unsigned long long)q);
        }
    }

    // Last block finalizes. Release: __threadfence before counter atomic.
    // Acquire: counter atomic + volatile reads of the integer bin totals.
    __shared__ unsigned int is_last;
    __threadfence();
    __syncthreads();
    if (threadIdx.x == 0)
        is_last = (atomicAdd(&g_done, 1u) == (unsigned)(GRID_B - 1)) ? 1u : 0u;
    __syncthreads();
    if (is_last && threadIdx.x == 0) {
        volatile int* vcnt = g_counts;
        volatile unsigned long long* vsum = g_sums;
        double acc = 0.0;
        int n = 0;
        for (int b = 0; b < NBINS; b++) {
            int c = vcnt[b];
            if (c > 0) {
                n++;
                acc += ((double)(long long)vsum[b] / SUM_SCALE) / (double)c;
            }
        }
        if (n < 1) n = 1;
        out[0] = (float)(acc / (double)n / 64.0 / 4096.0);
    }
}

// ---------------------------------------------------------------------------
extern "C" void kernel_launch(void* const* d_in, const int* in_sizes, int n_in,
                              void* d_out, int out_size)
{
    const float4* inp = (const float4*)d_in[0];
    const float4* tgt = (const float4*)d_in[1];
    float* out = (float*)d_out;
    int N = in_sizes[0] / 4;   // rows (C = 4 floats per row)
    if (N > MAXN) N = MAXN;

    init_kernel<<<1, 32>>>();
    passA_kernel<<<GRID_A, TPB>>>(inp, tgt, N);
    passB_kernel<<<GRID_B, TPB>>>(out, N);
}